// round 17
// baseline (speedup 1.0000x reference)
#include <cuda_runtime.h>
#include <cuda_fp16.h>
#include <math.h>
#include <stdint.h>

#define SS 512
#define BB 64
#define II 1024
#define HH 1024
#define SB (SS*BB)

// ---------------- scratch (static device globals; no allocation) -------------
__device__ float    g_XP[4ULL * SB * HH];        // input projections [4][S*B][H] fp32
__device__ uint32_t g_X16[16777216];             // x fp16 fragment-packed [256mt][64ch][128r][8]
__device__ uint32_t g_Hl16[16777216];            // h fp16 fragment-packed (outproj A)
__device__ uint32_t g_Wx16[2097152];             // Wx fp16 packed [4g][8cb][64ch][128n][8]
__device__ uint32_t g_Why16[524288];             // Why fp16 packed [8cb][64ch][128n][8]
__device__ uint32_t g_HTp16[2][32768];           // h fp16 fragment-packed ping-pong (recurrence)
__device__ uint32_t g_Wpk16[128ULL * 16384];     // fp16 packed recurrent weights (64KB/block)
__device__ unsigned g_chunkcnt[16];              // per-chunk-group step counters (monotonic)

// ---------------- helpers ----------------------------------------------------
__device__ __forceinline__ void mma_f16(float c[4], uint32_t a0, uint32_t a1,
                                        uint32_t a2, uint32_t a3,
                                        uint32_t b0, uint32_t b1) {
    asm volatile(
        "mma.sync.aligned.m16n8k16.row.col.f32.f16.f16.f32 "
        "{%0,%1,%2,%3}, {%4,%5,%6,%7}, {%8,%9}, {%0,%1,%2,%3};"
        : "+f"(c[0]), "+f"(c[1]), "+f"(c[2]), "+f"(c[3])
        : "r"(a0), "r"(a1), "r"(a2), "r"(a3), "r"(b0), "r"(b1));
}

__device__ __forceinline__ void cp_async16(uint32_t dst_smem, const void* src) {
    asm volatile("cp.async.cg.shared.global [%0], [%1], 16;" :: "r"(dst_smem), "l"(src));
}
__device__ __forceinline__ void cp_commit() { asm volatile("cp.async.commit_group;"); }
template<int N> __device__ __forceinline__ void cp_wait() {
    asm volatile("cp.async.wait_group %0;" :: "n"(N));
}

__device__ __forceinline__ uint32_t pack2h(float a, float b) {
    __half2 h = __floats2half2_rn(a, b);
    return *(uint32_t*)&h;
}

__device__ __forceinline__ void poll_cnt(int g, unsigned target) {
    const unsigned* p = &g_chunkcnt[g];
    unsigned v;
    while (true) {
        asm volatile("ld.acquire.gpu.u32 %0, [%1];" : "=r"(v) : "l"(p) : "memory");
        if (v >= target) break;
        __nanosleep(20);
    }
}

// ---------------- init / pack kernels ----------------------------------------
__global__ void init_state_kernel() {
    int idx = blockIdx.x * blockDim.x + threadIdx.x;
    if (idx < 32768) g_HTp16[0][idx] = 0u;
    if (idx < 16) g_chunkcnt[idx] = 0u;
}

// recurrence weights: u32 n = (((bx*64+chunk)*32+pcol)*4+c)*2+p
__global__ __launch_bounds__(256) void repack_w16(
    const float* __restrict__ Wi, const float* __restrict__ Wf,
    const float* __restrict__ Wc, const float* __restrict__ Wo)
{
    const float* W[4] = {Wi, Wf, Wc, Wo};
    int n = blockIdx.x * blockDim.x + threadIdx.x;   // 0..2097151
    int p     = n & 1;
    int c     = (n >> 1) & 3;
    int pcol  = (n >> 3) & 31;
    int chunk = (n >> 8) & 63;
    int bx    = n >> 14;
    int gate  = pcol >> 3;
    int col   = bx * 8 + (pcol & 7);
    int k     = chunk * 16 + 2 * c + 8 * p;
    g_Wpk16[n] = pack2h(W[gate][(size_t)k * HH + col],
                        W[gate][(size_t)(k + 1) * HH + col]);
}

// x packed as A-fragments: u32 idx = ((mt*64+ch)*128+row)*8 + c*2 + p
__global__ __launch_bounds__(256) void pack_x(const float* __restrict__ x) {
    int n = blockIdx.x * blockDim.x + threadIdx.x;   // 0..16777215
    int p   = n & 1;
    int c   = (n >> 1) & 3;
    int row = (n >> 3) & 127;
    int ch  = (n >> 10) & 63;
    int mt  = n >> 16;
    size_t R = (size_t)mt * 128 + row;
    int k = ch * 16 + 2 * c + 8 * p;
    const float* src = x + R * II + k;
    g_X16[n] = pack2h(src[0], src[1]);
}

// Wx packed as B-fragments: u32 idx = (((g*8+cb)*64+ch)*128+nn)*8 + c*2 + p
__global__ __launch_bounds__(256) void pack_wx(
    const float* __restrict__ W0, const float* __restrict__ W1,
    const float* __restrict__ W2, const float* __restrict__ W3)
{
    const float* W[4] = {W0, W1, W2, W3};
    int n = blockIdx.x * blockDim.x + threadIdx.x;   // 0..2097151
    int p  = n & 1;
    int c  = (n >> 1) & 3;
    int nn = (n >> 3) & 127;
    int ch = (n >> 10) & 63;
    int cb = (n >> 16) & 7;
    int g  = n >> 19;
    int col = cb * 128 + nn;
    int k   = ch * 16 + 2 * c + 8 * p;
    g_Wx16[n] = pack2h(W[g][(size_t)k * HH + col],
                       W[g][(size_t)(k + 1) * HH + col]);
}

__global__ __launch_bounds__(256) void pack_why(const float* __restrict__ Why) {
    int n = blockIdx.x * blockDim.x + threadIdx.x;   // 0..524287
    int p  = n & 1;
    int c  = (n >> 1) & 3;
    int nn = (n >> 3) & 127;
    int ch = (n >> 10) & 63;
    int cb = n >> 16;
    int col = cb * 128 + nn;
    int k   = ch * 16 + 2 * c + 8 * p;
    g_Why16[n] = pack2h(Why[(size_t)k * HH + col],
                        Why[(size_t)(k + 1) * HH + col]);
}

// ---------------- big fp16 GEMM, cp.async 3-stage (R15-proven) ---------------
#define GSTG 4096
#define GST 3

__device__ __forceinline__ void gemm_f16_core(
    const uint32_t* __restrict__ A, const uint32_t* __restrict__ Bw,
    const float* __restrict__ bias, float* __restrict__ C)
{
    extern __shared__ __align__(16) uint32_t gsm[];
    uint32_t* Asm = gsm;
    uint32_t* Bsm = gsm + GST * GSTG;

    const int tid  = threadIdx.x;
    const int lane = tid & 31;
    const int w    = tid >> 5;
    const int wm   = w & 1;
    const int wn   = w >> 1;

    const uint32_t* Ab = A  + (size_t)blockIdx.y * 65536;
    const uint32_t* Bb = Bw + (size_t)blockIdx.x * 65536;
    const int m0 = blockIdx.y * 128;
    const int n0 = blockIdx.x * 128;

    const uint32_t sA = (uint32_t)__cvta_generic_to_shared(Asm);
    const uint32_t sB = (uint32_t)__cvta_generic_to_shared(Bsm);

    float acc[4][4][4];
    #pragma unroll
    for (int i = 0; i < 4; ++i)
        #pragma unroll
        for (int j = 0; j < 4; ++j)
            #pragma unroll
            for (int r = 0; r < 4; ++r) acc[i][j][r] = 0.0f;

    auto issue = [&](int it, int slot) {
        const uint32_t* As = Ab + it * GSTG;
        const uint32_t* Bs = Bb + it * GSTG;
        #pragma unroll
        for (int j = 0; j < 4; ++j) {
            int idx = (tid + 256 * j) * 4;
            cp_async16(sA + (slot * GSTG + idx) * 4, As + idx);
            cp_async16(sB + (slot * GSTG + idx) * 4, Bs + idx);
        }
    };

    issue(0, 0); cp_commit();
    issue(1, 1); cp_commit();

    const int arow = wm * 64 + (lane >> 2);
    const int acp  = (lane & 3) * 2;

    for (int it = 0; it < 16; ++it) {
        cp_wait<1>();
        __syncthreads();
        if (it + 2 < 16) issue(it + 2, (it + 2) % GST);
        cp_commit();

        const uint32_t* As = Asm + (it % GST) * GSTG;
        const uint32_t* Bs = Bsm + (it % GST) * GSTG;

        #pragma unroll
        for (int ch = 0; ch < 4; ++ch) {
            uint2 afa[4], afb[4];
            #pragma unroll
            for (int mt = 0; mt < 4; ++mt) {
                int base = (ch * 128 + arow + mt * 16) * 8 + acp;
                afa[mt] = *(const uint2*)(As + base);
                afb[mt] = *(const uint2*)(As + base + 64);
            }
            uint2 bf[4];
            #pragma unroll
            for (int nt = 0; nt < 4; ++nt) {
                int nb = (ch * 128 + wn * 32 + nt * 8 + (lane >> 2)) * 8 + acp;
                bf[nt] = *(const uint2*)(Bs + nb);
            }
            #pragma unroll
            for (int mt = 0; mt < 4; ++mt)
                #pragma unroll
                for (int nt = 0; nt < 4; ++nt)
                    mma_f16(acc[mt][nt], afa[mt].x, afb[mt].x,
                            afa[mt].y, afb[mt].y, bf[nt].x, bf[nt].y);
        }
    }

    #pragma unroll
    for (int mt = 0; mt < 4; ++mt) {
        int row = m0 + wm * 64 + mt * 16 + (lane >> 2);
        #pragma unroll
        for (int nt = 0; nt < 4; ++nt) {
            int col = n0 + wn * 32 + nt * 8 + 2 * (lane & 3);
            float b0 = bias[col], b1 = bias[col + 1];
            float2 v0 = {acc[mt][nt][0] + b0, acc[mt][nt][1] + b1};
            float2 v1 = {acc[mt][nt][2] + b0, acc[mt][nt][3] + b1};
            *(float2*)&C[(size_t)row * HH + col]       = v0;
            *(float2*)&C[(size_t)(row + 8) * HH + col] = v1;
        }
    }
}

__global__ __launch_bounds__(256) void gemm_xproj_f16(
    const float* __restrict__ b0, const float* __restrict__ b1,
    const float* __restrict__ b2, const float* __restrict__ b3)
{
    const float* bs[4] = {b0, b1, b2, b3};
    int g = blockIdx.z;
    gemm_f16_core(g_X16, g_Wx16 + (size_t)g * 524288, bs[g],
                  g_XP + (size_t)g * SB * HH);
}

__global__ __launch_bounds__(256) void gemm_outproj_f16(
    const float* __restrict__ bias, float* __restrict__ out)
{
    gemm_f16_core(g_Hl16, g_Why16, bias, out);
}

// ---------------- Persistent recurrence kernel (fp16, chunk-flag dataflow) ---
// 128 blocks x 512 threads (16 warps), 1 block/SM.
// NO global barrier: producers release per-chunk-group counters after writing
// h; consumers poll cnt[stage] >= 8*t before issuing that stage's cp.async.
// Stage issue: warps 12-15 (1/4 each + poll). XP prefetch: warps 0-3 at it==0.
#define PST 6
#define PNIT 16
#define REDW 2176   // 64*34

__global__ __launch_bounds__(512) void lstm_persist(
    const float* __restrict__ bi, const float* __restrict__ bf,
    const float* __restrict__ bc, const float* __restrict__ bo)
{
    extern __shared__ __align__(16) uint32_t smu[];
    uint32_t* Wsm16 = smu;                         // 16384 u32 (64KB)
    uint32_t* Asm32 = smu + 16384;                 // 6*2048 u32 (48KB, alias red)
    float*    XPsm  = (float*)(smu + 16384 + PST * 2048);  // 2*2048 f
    float*    pre   = XPsm + 4096;                 // 2176 f
    float*    red   = (float*)Asm32;               // red[3][64][34]

    const int tid  = threadIdx.x;
    const int lane = tid & 31;
    const int w    = tid >> 5;
    const int wm   = w & 3;
    const int wk   = w >> 2;
    const int bx   = blockIdx.x;
    const int c0   = bx * 8;

    const uint32_t sW = (uint32_t)__cvta_generic_to_shared(Wsm16);
    const uint32_t sA = (uint32_t)__cvta_generic_to_shared(Asm32);
    const uint32_t sX = (uint32_t)__cvta_generic_to_shared(XPsm);

    // ---- load fp16 weights + XP(step0), then drain so group counts are clean
    {
        const uint32_t* Wsrc = g_Wpk16 + (size_t)bx * 16384;
        #pragma unroll 4
        for (int j = 0; j < 8; ++j) {
            int idx = tid + 512 * j;
            cp_async16(sW + idx * 16, Wsrc + idx * 4);
        }
        int gate = tid >> 7, r2 = (tid >> 1) & 63, half = tid & 1;
        const float* src = g_XP + (size_t)gate * SB * HH
                         + (size_t)r2 * HH + c0 + half * 4;
        cp_async16(sX + (gate * 512 + r2 * 8 + half * 4) * 4, src);
    }
    cp_commit();
    cp_wait<0>();
    __syncthreads();

    const int cc  = tid & 7;
    const int col = c0 + cc;
    const int row = tid >> 3;            // 0..63
    const float bI = bi[col], bF = bf[col], bC = bc[col], bO = bo[col];
    const int hchunk = col >> 4;
    const int hkk    = col & 15;
    const int hp     = hkk >> 3;
    const int hc     = (hkk & 7) >> 1;
    const int hd     = hkk & 1;
    const int hidx   = ((hchunk * 64 + row) * 4 + hc) * 4 + hp * 2 + hd;  // half idx
    float creg = 0.0f;

    const int aoff = ((wm * 16 + (lane >> 2)) * 4 + (lane & 3)) * 2 + wk * 512;
    const int nrow = lane >> 2;
    const int bcc  = lane & 3;
    const int q    = w - 12;             // stage-issue quarter (warps 12-15)

    for (int t = 0; t < SS; ++t) {
        const uint32_t* Asrc = g_HTp16[t & 1];
        uint16_t*       hTn  = (uint16_t*)g_HTp16[(t + 1) & 1];
        uint16_t* hAll = (uint16_t*)g_Hl16;
        const int mt128   = t >> 1;
        const int row128  = ((t & 1) << 6) + row;
        const size_t hallidx = ((((size_t)mt128 * 64 + hchunk) * 128 + row128) * 8
                                + hc * 2 + hp) * 2 + hd;
        const unsigned target = 8u * (unsigned)t;

        float acc[4][4];
        #pragma unroll
        for (int nt = 0; nt < 4; ++nt)
            #pragma unroll
            for (int r = 0; r < 4; ++r) acc[nt][r] = 0.0f;

        // ---- prologue: warps 12-15 poll + issue stages 0..PST-2 -------------
        if (w >= 12) {
            #pragma unroll
            for (int i = 0; i < PST - 1; ++i) {
                poll_cnt(i, target);
                #pragma unroll
                for (int j = 0; j < 4; ++j) {
                    int idx = (q * 128 + j * 32 + lane) * 4;
                    cp_async16(sA + ((i % PST) * 2048 + idx) * 4,
                               Asrc + i * 2048 + idx);
                }
                cp_commit();
            }
        }

        for (int it = 0; it < PNIT; ++it) {
            if (w >= 12) cp_wait<PST - 2>();
            __syncthreads();
            if (w >= 12) {
                int i = it + PST - 1;
                if (i < PNIT) {
                    poll_cnt(i, target);
                    #pragma unroll
                    for (int j = 0; j < 4; ++j) {
                        int idx = (q * 128 + j * 32 + lane) * 4;
                        cp_async16(sA + ((i % PST) * 2048 + idx) * 4,
                                   Asrc + i * 2048 + idx);
                    }
                }
                cp_commit();   // possibly empty group — keeps counts uniform
            }
            if (w < 4 && it == 0 && t + 1 < SS) {
                int buf = (t + 1) & 1;
                #pragma unroll
                for (int j = 0; j < 4; ++j) {
                    int vt = w * 128 + j * 32 + lane;       // 0..511
                    int gate = vt >> 7, r2 = (vt >> 1) & 63, half = vt & 1;
                    const float* src = g_XP + (size_t)gate * SB * HH
                                     + ((size_t)(t + 1) * BB + r2) * HH + c0 + half * 4;
                    cp_async16(sX + (buf * 2048 + gate * 512 + r2 * 8 + half * 4) * 4, src);
                }
                cp_commit();
            }

            const uint32_t* Asl = Asm32 + (it % PST) * 2048;
            const int chunk = it * 4 + wk;

            uint2 a01 = *(const uint2*)(Asl + aoff);
            uint2 a23 = *(const uint2*)(Asl + aoff + 64);
            #pragma unroll
            for (int nt = 0; nt < 4; ++nt) {
                const uint32_t* Bb = Wsm16 + ((chunk * 32 + nt * 8 + nrow) * 4 + bcc) * 2;
                uint2 b = *(const uint2*)Bb;
                mma_f16(acc[nt], a01.x, a23.x, a01.y, a23.y, b.x, b.y);
            }
        }

        cp_wait<0>();
        __syncthreads();

        // ---- 4-way k reduction ----
        if (wk > 0) {
            #pragma unroll
            for (int nt = 0; nt < 4; ++nt) {
                int r0 = wm * 16 + (lane >> 2);
                int cr = nt * 8 + 2 * (lane & 3);
                *(float2*)&red[(wk - 1) * REDW + r0 * 34 + cr]
                    = make_float2(acc[nt][0], acc[nt][1]);
                *(float2*)&red[(wk - 1) * REDW + (r0 + 8) * 34 + cr]
                    = make_float2(acc[nt][2], acc[nt][3]);
            }
        }
        __syncthreads();
        if (wk == 0) {
            #pragma unroll
            for (int nt = 0; nt < 4; ++nt) {
                int r0 = wm * 16 + (lane >> 2);
                int cr = nt * 8 + 2 * (lane & 3);
                float2 s0 = make_float2(acc[nt][0], acc[nt][1]);
                float2 s1 = make_float2(acc[nt][2], acc[nt][3]);
                #pragma unroll
                for (int p = 0; p < 3; ++p) {
                    float2 u0 = *(const float2*)&red[p * REDW + r0 * 34 + cr];
                    float2 u1 = *(const float2*)&red[p * REDW + (r0 + 8) * 34 + cr];
                    s0.x += u0.x; s0.y += u0.y;
                    s1.x += u1.x; s1.y += u1.y;
                }
                *(float2*)&pre[r0 * 34 + cr]       = s0;
                *(float2*)&pre[(r0 + 8) * 34 + cr] = s1;
            }
        }
        __syncthreads();

        // ---- fused elementwise epilogue ----
        const float* xp = XPsm + (t & 1) * 2048;
        {
            int b0 = row * 34 + cc;

            float pi = pre[b0]      + xp[0 * 512 + row * 8 + cc] + bI;
            float pf = pre[b0 + 8]  + xp[1 * 512 + row * 8 + cc] + bF;
            float pc = pre[b0 + 16] + xp[2 * 512 + row * 8 + cc] + bC;
            float po = pre[b0 + 24] + xp[3 * 512 + row * 8 + cc] + bO;

            float iv = 1.0f / (1.0f + expf(-pi));
            float fv = 1.0f / (1.0f + expf(-pf));
            float ov = 1.0f / (1.0f + expf(-po));
            float gv = tanhf(pc);

            float cv = fv * creg + iv * gv;
            float hv = ov * tanhf(cv);
            creg = cv;

            uint16_t h16 = __half_as_ushort(__float2half(hv));
            hTn[hidx]     = h16;
            hAll[hallidx] = h16;
        }

        // ---- producer arrive (NO wait) ----
        __threadfence();
        __syncthreads();
        if (tid == 0) atomicAdd(&g_chunkcnt[bx >> 3], 1u);
    }
}

// ---------------- launch -----------------------------------------------------
extern "C" void kernel_launch(void* const* d_in, const int* in_sizes, int n_in,
                              void* d_out, int out_size)
{
    (void)in_sizes; (void)n_in; (void)out_size;

    const float* x    = (const float*)d_in[0];
    const float* Wx[4] = {(const float*)d_in[1], (const float*)d_in[3],
                          (const float*)d_in[5], (const float*)d_in[7]};
    const float* bx[4] = {(const float*)d_in[2], (const float*)d_in[4],
                          (const float*)d_in[6], (const float*)d_in[8]};
    const float* Wh[4] = {(const float*)d_in[9],  (const float*)d_in[11],
                          (const float*)d_in[13], (const float*)d_in[15]};
    const float* bh[4] = {(const float*)d_in[10], (const float*)d_in[12],
                          (const float*)d_in[14], (const float*)d_in[16]};
    const float* Why = (const float*)d_in[17];
    const float* bhy = (const float*)d_in[18];
    float* out = (float*)d_out;

    static int smem_set = 0;
    const int psmem = (16384 + PST * 2048 + 2 * 2048 + REDW) * 4;
    const int gsmem = GST * 2 * GSTG * 4;   // 96KB
    if (!smem_set) {
        cudaFuncSetAttribute(lstm_persist,
                             cudaFuncAttributeMaxDynamicSharedMemorySize, psmem);
        cudaFuncSetAttribute(gemm_xproj_f16,
                             cudaFuncAttributeMaxDynamicSharedMemorySize, gsmem);
        cudaFuncSetAttribute(gemm_outproj_f16,
                             cudaFuncAttributeMaxDynamicSharedMemorySize, gsmem);
        smem_set = 1;
    }

    init_state_kernel<<<(32768 + 256) / 256, 256>>>();
    repack_w16<<<2097152 / 256, 256>>>(Wh[0], Wh[1], Wh[2], Wh[3]);
    pack_x<<<16777216 / 256, 256>>>(x);
    pack_wx<<<2097152 / 256, 256>>>(Wx[0], Wx[1], Wx[2], Wx[3]);
    pack_why<<<524288 / 256, 256>>>(Why);

    // input projections: XP[g] = x @ W_x[g] + b_x[g]
    {
        dim3 grid(8, 256, 4);
        gemm_xproj_f16<<<grid, 256, gsmem>>>(bx[0], bx[1], bx[2], bx[3]);
    }

    lstm_persist<<<128, 512, psmem>>>(bh[0], bh[1], bh[2], bh[3]);

    // output projection: Y = H_all @ W_hy + b_hy
    {
        dim3 grid(8, 256);
        gemm_outproj_f16<<<grid, 256, gsmem>>>(bhy, out);
    }
}